// round 10
// baseline (speedup 1.0000x reference)
#include <cuda_runtime.h>
#include <cuda_bf16.h>
#include <cstdint>

// Problem constants
#define BATCH 4
#define SEQ   2048
#define DMODEL 1024
#define NHEADS 16
#define HD    64
#define ROWS  (BATCH * SEQ)          // 8192
#define QKV_N (3 * DMODEL)           // 3072

// Scratch (allocation-free rule: __device__ globals)
__device__ float g_qkv[(size_t)ROWS * QKV_N];
__device__ float g_att[(size_t)ROWS * DMODEL];
__device__ uint32_t g_kh[(size_t)BATCH * NHEADS * SEQ * 32];   // packed bf16 hi
__device__ uint32_t g_kl[(size_t)BATCH * NHEADS * SEQ * 32];   // packed bf16 lo

// ---------------------------------------------------------------------------
// helpers
// ---------------------------------------------------------------------------
__device__ __forceinline__ uint32_t s2u(const void* p) {
    uint32_t a;
    asm("{ .reg .u64 t; cvta.to.shared.u64 t, %1; cvt.u32.u64 %0, t; }"
        : "=r"(a) : "l"(p));
    return a;
}
__device__ __forceinline__ uint32_t tf32u(float x) {
    uint32_t u; asm("cvt.rn.tf32.f32 %0, %1;" : "=r"(u) : "f"(x)); return u;
}
__device__ __forceinline__ float tf32f(float x) { return __uint_as_float(tf32u(x)); }

__device__ __forceinline__ void mma_tf32(float& d0, float& d1, float& d2, float& d3,
                                         uint32_t a0, uint32_t a1, uint32_t a2, uint32_t a3,
                                         uint32_t b0, uint32_t b1)
{
    asm volatile(
        "mma.sync.aligned.m16n8k8.row.col.f32.tf32.tf32.f32 "
        "{%0,%1,%2,%3}, {%4,%5,%6,%7}, {%8,%9}, {%0,%1,%2,%3};"
        : "+f"(d0), "+f"(d1), "+f"(d2), "+f"(d3)
        : "r"(a0), "r"(a1), "r"(a2), "r"(a3), "r"(b0), "r"(b1));
}

__device__ __forceinline__ void mma_bf16(float& d0, float& d1, float& d2, float& d3,
                                         uint32_t a0, uint32_t a1, uint32_t a2, uint32_t a3,
                                         uint32_t b0, uint32_t b1)
{
    asm volatile(
        "mma.sync.aligned.m16n8k16.row.col.f32.bf16.bf16.f32 "
        "{%0,%1,%2,%3}, {%4,%5,%6,%7}, {%8,%9}, {%0,%1,%2,%3};"
        : "+f"(d0), "+f"(d1), "+f"(d2), "+f"(d3)
        : "r"(a0), "r"(a1), "r"(a2), "r"(a3), "r"(b0), "r"(b1));
}

__device__ __forceinline__ void cpasync16(uint32_t dst, const void* src) {
    asm volatile("cp.async.cg.shared.global [%0], [%1], 16;" :: "r"(dst), "l"(src));
}
#define CP_COMMIT() asm volatile("cp.async.commit_group;" ::: "memory")
#define CP_WAIT0()  asm volatile("cp.async.wait_group 0;" ::: "memory")
#define CP_WAIT1()  asm volatile("cp.async.wait_group 1;" ::: "memory")

// pack two floats -> bf16x2 + low-part extraction
__device__ __forceinline__ uint32_t bfpack(float a, float b) {
    __nv_bfloat162 h = __floats2bfloat162_rn(a, b);
    return *reinterpret_cast<uint32_t*>(&h);
}
__device__ __forceinline__ float bflo(uint32_t u) { return __uint_as_float(u << 16); }
__device__ __forceinline__ float bfhi(uint32_t u) { return __uint_as_float(u & 0xFFFF0000u); }

// ---------------------------------------------------------------------------
// TF32 GEMM — exact round-2/3/6 kernel (419us QKV, known good; do not touch)
// ---------------------------------------------------------------------------
#define BM 128
#define BN 128
#define BKK 16
#define AST 20
#define BST 136

__global__ void __launch_bounds__(256, 2) tf32_gemm_kernel(
    const float* __restrict__ A, const float* __restrict__ B,
    const float* __restrict__ bias, float* __restrict__ C,
    int M, int N, int K)
{
    __shared__ float As[BM][AST];
    __shared__ float Bs[BKK][BST];

    const int tid  = threadIdx.x;
    const int lane = tid & 31;
    const int warp = tid >> 5;
    const int brow = blockIdx.y;
    const int bcol = blockIdx.x;

    const int am0 = tid >> 2;
    const int aq  = (tid & 3) * 4;
    const int bk0 = tid >> 5;
    const int bn0 = (tid & 31) * 4;

    const int wrow = warp >> 2;
    const int wcol = warp & 3;
    const int mbase = wrow * 64;
    const int nbase = wcol * 32;
    const int r = lane >> 2;
    const int c = lane & 3;

    const float* Ab = A + (size_t)brow * BM * K;
    const float* Bb = B + (size_t)bcol * BN;

    float acc[4][4][4];
    #pragma unroll
    for (int i = 0; i < 4; i++)
        #pragma unroll
        for (int j = 0; j < 4; j++)
            #pragma unroll
            for (int t = 0; t < 4; t++) acc[i][j][t] = 0.f;

    float4 pa0 = *(const float4*)(Ab + (size_t)am0 * K + aq);
    float4 pa1 = *(const float4*)(Ab + (size_t)(am0 + 64) * K + aq);
    float4 pb0 = *(const float4*)(Bb + (size_t)bk0 * N + bn0);
    float4 pb1 = *(const float4*)(Bb + (size_t)(bk0 + 8) * N + bn0);

    for (int k0 = 0; k0 < K; k0 += BKK) {
        *(float4*)&As[am0][aq] = make_float4(tf32f(pa0.x), tf32f(pa0.y), tf32f(pa0.z), tf32f(pa0.w));
        *(float4*)&As[am0 + 64][aq] = make_float4(tf32f(pa1.x), tf32f(pa1.y), tf32f(pa1.z), tf32f(pa1.w));
        *(float4*)&Bs[bk0][bn0] = make_float4(tf32f(pb0.x), tf32f(pb0.y), tf32f(pb0.z), tf32f(pb0.w));
        *(float4*)&Bs[bk0 + 8][bn0] = make_float4(tf32f(pb1.x), tf32f(pb1.y), tf32f(pb1.z), tf32f(pb1.w));
        __syncthreads();

        if (k0 + BKK < K) {
            pa0 = *(const float4*)(Ab + (size_t)am0 * K + k0 + BKK + aq);
            pa1 = *(const float4*)(Ab + (size_t)(am0 + 64) * K + k0 + BKK + aq);
            pb0 = *(const float4*)(Bb + (size_t)(k0 + BKK + bk0) * N + bn0);
            pb1 = *(const float4*)(Bb + (size_t)(k0 + BKK + bk0 + 8) * N + bn0);
        }

        #pragma unroll
        for (int ks = 0; ks < 2; ks++) {
            const int kb = ks * 8;
            uint32_t af[4][4];
            #pragma unroll
            for (int mt = 0; mt < 4; mt++) {
                const int m = mbase + mt * 16;
                af[mt][0] = __float_as_uint(As[m + r][kb + c]);
                af[mt][1] = __float_as_uint(As[m + r + 8][kb + c]);
                af[mt][2] = __float_as_uint(As[m + r][kb + c + 4]);
                af[mt][3] = __float_as_uint(As[m + r + 8][kb + c + 4]);
            }
            uint32_t bf[4][2];
            #pragma unroll
            for (int nt = 0; nt < 4; nt++) {
                const int n = nbase + nt * 8 + r;
                bf[nt][0] = __float_as_uint(Bs[kb + c][n]);
                bf[nt][1] = __float_as_uint(Bs[kb + c + 4][n]);
            }
            #pragma unroll
            for (int mt = 0; mt < 4; mt++)
                #pragma unroll
                for (int nt = 0; nt < 4; nt++)
                    mma_tf32(acc[mt][nt][0], acc[mt][nt][1],
                             acc[mt][nt][2], acc[mt][nt][3],
                             af[mt][0], af[mt][1], af[mt][2], af[mt][3],
                             bf[nt][0], bf[nt][1]);
        }
        __syncthreads();
    }

    #pragma unroll
    for (int mt = 0; mt < 4; mt++) {
        const int row0 = brow * BM + mbase + mt * 16 + r;
        #pragma unroll
        for (int nt = 0; nt < 4; nt++) {
            const int col = bcol * BN + nbase + nt * 8 + 2 * c;
            float2 v0 = make_float2(acc[mt][nt][0], acc[mt][nt][1]);
            float2 v1 = make_float2(acc[mt][nt][2], acc[mt][nt][3]);
            if (bias) {
                float2 bb = *(const float2*)(bias + col);
                v0.x += bb.x; v0.y += bb.y;
                v1.x += bb.x; v1.y += bb.y;
            }
            *(float2*)(C + (size_t)row0 * N + col)       = v0;
            *(float2*)(C + (size_t)(row0 + 8) * N + col) = v1;
        }
    }
}

// ---------------------------------------------------------------------------
// prep kernels (between QKV GEMM and flash)
// ---------------------------------------------------------------------------
// K section of qkv -> packed bf16 hi/lo, laid out [bh][row][32 u32]
__global__ void prep_k_kernel(const float* __restrict__ qkv,
                              uint32_t* __restrict__ kh, uint32_t* __restrict__ kl)
{
    const int idx = blockIdx.x * blockDim.x + threadIdx.x;   // bh*2048*32 items
    const int j   = idx & 31;
    const int row = (idx >> 5) & (SEQ - 1);
    const int bh  = idx >> 16;
    const int b = bh >> 4, h = bh & 15;
    float2 v = *(const float2*)(qkv + ((size_t)(b * SEQ + row)) * QKV_N
                                + DMODEL + h * HD + 2 * j);
    uint32_t hu = bfpack(v.x, v.y);
    kh[idx] = hu;
    kl[idx] = bfpack(v.x - bflo(hu), v.y - bfhi(hu));
}

// V section of qkv -> tf32-rounded in place (idempotent per graph replay:
// QKV GEMM rewrites this region before each invocation)
__global__ void round_v_kernel(float* __restrict__ qkv)
{
    const int idx = blockIdx.x * blockDim.x + threadIdx.x;   // bh*2048*16 float4s
    const int c4  = (idx & 15) * 4;
    const int row = (idx >> 4) & (SEQ - 1);
    const int bh  = idx >> 15;
    const int b = bh >> 4, h = bh & 15;
    float* p = qkv + ((size_t)(b * SEQ + row)) * QKV_N + 2 * DMODEL + h * HD + c4;
    float4 v = *(const float4*)p;
    *(float4*)p = make_float4(tf32f(v.x), tf32f(v.y), tf32f(v.z), tf32f(v.w));
}

// ---------------------------------------------------------------------------
// Flash attention v5, causal. Compute path identical to round 9 (bf16 3-split
// S, tf32 PV, shuffle relayout). Loader: pure cp.async (K pre-split, V
// pre-rounded), double-buffered K/V stages.
// smem: Q 36864 + 2 * (Kh 9216 + Kl 9216 + V 18432) = 110592 B -> 2 CTAs/SM.
// ---------------------------------------------------------------------------
#define FBM 128
#define FBN 64
#define QBST 36
#define KBST 36
#define VST 72
#define KV_U32 (2 * FBN * KBST + FBN * VST)                 // 9216 u32 per stage
#define FLASH_SMEM ((2 * FBM * QBST + 2 * KV_U32) * 4)      // 110592 B

__global__ void __launch_bounds__(256, 2) flash_tc_kernel(
    const float* __restrict__ qkv,
    const uint32_t* __restrict__ gkh, const uint32_t* __restrict__ gkl,
    float* __restrict__ out)
{
    extern __shared__ uint32_t smf[];
    uint32_t* Qh  = smf;
    uint32_t* Ql  = Qh + FBM * QBST;
    uint32_t* KV0 = Ql + FBM * QBST;

    const int tid  = threadIdx.x;
    const int lane = tid & 31;
    const int warp = tid >> 5;
    const int qt = (int)gridDim.x - 1 - (int)blockIdx.x;   // big blocks first
    const int bh = blockIdx.y;
    const int b  = bh >> 4;
    const int h  = bh & 15;

    const size_t rs = (size_t)QKV_N;
    const float* qb = qkv + (size_t)b * SEQ * rs + h * HD;
    const float* vb = qb + 2 * DMODEL;
    const uint32_t* khb = gkh + (size_t)bh * SEQ * 32;
    const uint32_t* klb = gkl + (size_t)bh * SEQ * 32;
    const int q0 = qt * FBM;

    // ---- Q prologue: load fp32, split to bf16 hi/lo, pack pairs ----
    for (int idx = tid; idx < FBM * 32; idx += 256) {
        const int row = idx >> 5, j = idx & 31;
        float2 q = *(const float2*)(qb + (size_t)(q0 + row) * rs + 2 * j);
        uint32_t hu = bfpack(q.x, q.y);
        Qh[row * QBST + j] = hu;
        Ql[row * QBST + j] = bfpack(q.x - bflo(hu), q.y - bfhi(hu));
    }

    auto load_kv = [&](int kt, int buf) {
        uint32_t* Khs = KV0 + buf * KV_U32;
        uint32_t* Kls = Khs + FBN * KBST;
        float*    Vss = (float*)(Kls + FBN * KBST);
        // Kh/Kl: 64 rows x 128B -> 8 cp16 per row per array
        for (int idx = tid; idx < FBN * 8; idx += 256) {
            const int row = idx >> 3, j4 = (idx & 7) * 4;
            const size_t go = ((size_t)(kt * FBN + row)) * 32 + j4;
            cpasync16(s2u(&Khs[row * KBST + j4]), khb + go);
            cpasync16(s2u(&Kls[row * KBST + j4]), klb + go);
        }
        // V: 64 rows x 256B fp32 -> 16 cp16 per row
        for (int idx = tid; idx < FBN * 16; idx += 256) {
            const int rr = idx >> 4, ch = (idx & 15) * 4;
            cpasync16(s2u(&Vss[rr * VST + ch]),
                      vb + (size_t)(kt * FBN + rr) * rs + ch);
        }
        CP_COMMIT();
    };

    const int r = lane >> 2;       // 0..7
    const int c = lane & 3;        // 0..3
    const int m0 = warp * 16;

    float o[8][4];
    #pragma unroll
    for (int nt = 0; nt < 8; nt++)
        #pragma unroll
        for (int t = 0; t < 4; t++) o[nt][t] = 0.f;
    float mx0 = -1e30f, mx1 = -1e30f, l0 = 0.f, l1 = 0.f;
    const float sl2e = 0.125f * 1.4426950408889634f;

    const int nkt = 2 * qt + 2;
    load_kv(0, 0);

    for (int kt = 0; kt < nkt; kt++) {
        const int buf = kt & 1;
        if (kt + 1 < nkt) { load_kv(kt + 1, 1 - buf); CP_WAIT1(); }
        else              { CP_WAIT0(); }
        __syncthreads();   // stage[buf] ready; covers Q stores on iter 0

        const uint32_t* Kh = KV0 + buf * KV_U32;
        const uint32_t* Kl = Kh + FBN * KBST;
        const float*    Vs = (const float*)(Kl + FBN * KBST);

        // ---- S = Q @ K^T : bf16 3-split (identical to round 9) ----
        float s[8][4];
        #pragma unroll
        for (int nt = 0; nt < 8; nt++)
            #pragma unroll
            for (int t = 0; t < 4; t++) s[nt][t] = 0.f;

        #pragma unroll
        for (int g = 0; g < 4; g++) {
            const int qo = 8 * g + c;
            uint32_t ah0 = Qh[(m0 + r) * QBST + qo];
            uint32_t ah1 = Qh[(m0 + r + 8) * QBST + qo];
            uint32_t ah2 = Qh[(m0 + r) * QBST + qo + 4];
            uint32_t ah3 = Qh[(m0 + r + 8) * QBST + qo + 4];
            uint32_t al0 = Ql[(m0 + r) * QBST + qo];
            uint32_t al1 = Ql[(m0 + r + 8) * QBST + qo];
            uint32_t al2 = Ql[(m0 + r) * QBST + qo + 4];
            uint32_t al3 = Ql[(m0 + r + 8) * QBST + qo + 4];
            #pragma unroll
            for (int half = 0; half < 2; half++) {
                uint32_t bhf[4][2], blf[4][2];
                #pragma unroll
                for (int q2 = 0; q2 < 4; q2++) {
                    const int n = (half * 4 + q2) * 8 + r;
                    bhf[q2][0] = Kh[n * KBST + qo];
                    bhf[q2][1] = Kh[n * KBST + qo + 4];
                    blf[q2][0] = Kl[n * KBST + qo];
                    blf[q2][1] = Kl[n * KBST + qo + 4];
                }
                #pragma unroll
                for (int q2 = 0; q2 < 4; q2++) {
                    const int nt = half * 4 + q2;
                    mma_bf16(s[nt][0], s[nt][1], s[nt][2], s[nt][3],
                             ah0, ah1, ah2, ah3, bhf[q2][0], bhf[q2][1]);
                }
                #pragma unroll
                for (int q2 = 0; q2 < 4; q2++) {
                    const int nt = half * 4 + q2;
                    mma_bf16(s[nt][0], s[nt][1], s[nt][2], s[nt][3],
                             ah0, ah1, ah2, ah3, blf[q2][0], blf[q2][1]);
                }
                #pragma unroll
                for (int q2 = 0; q2 < 4; q2++) {
                    const int nt = half * 4 + q2;
                    mma_bf16(s[nt][0], s[nt][1], s[nt][2], s[nt][3],
                             al0, al1, al2, al3, bhf[q2][0], bhf[q2][1]);
                }
            }
        }

        // ---- causal mask ----
        if (kt >= 2 * qt) {
            const int q0i = q0 + m0 + r;
            #pragma unroll
            for (int nt = 0; nt < 8; nt++) {
                int k0i = kt * FBN + nt * 8 + 2 * c;
                if (k0i     > q0i)     s[nt][0] = -1e30f;
                if (k0i + 1 > q0i)     s[nt][1] = -1e30f;
                if (k0i     > q0i + 8) s[nt][2] = -1e30f;
                if (k0i + 1 > q0i + 8) s[nt][3] = -1e30f;
            }
        }

        // ---- online softmax: row r ----
        {
            float t = -1e30f;
            #pragma unroll
            for (int nt = 0; nt < 8; nt++) t = fmaxf(t, fmaxf(s[nt][0], s[nt][1]));
            t = fmaxf(t, __shfl_xor_sync(0xffffffffu, t, 1));
            t = fmaxf(t, __shfl_xor_sync(0xffffffffu, t, 2));
            t *= sl2e;
            float mn = fmaxf(mx0, t);
            float alpha = exp2f(mx0 - mn);
            float ps = 0.f;
            #pragma unroll
            for (int nt = 0; nt < 8; nt++) {
                float p0 = exp2f(s[nt][0] * sl2e - mn);
                float p1 = exp2f(s[nt][1] * sl2e - mn);
                s[nt][0] = p0; s[nt][1] = p1; ps += p0 + p1;
            }
            ps += __shfl_xor_sync(0xffffffffu, ps, 1);
            ps += __shfl_xor_sync(0xffffffffu, ps, 2);
            l0 = l0 * alpha + ps; mx0 = mn;
            #pragma unroll
            for (int nt = 0; nt < 8; nt++) { o[nt][0] *= alpha; o[nt][1] *= alpha; }
        }
        // ---- row r+8 ----
        {
            float t = -1e30f;
            #pragma unroll
            for (int nt = 0; nt < 8; nt++) t = fmaxf(t, fmaxf(s[nt][2], s[nt][3]));
            t = fmaxf(t, __shfl_xor_sync(0xffffffffu, t, 1));
            t = fmaxf(t, __shfl_xor_sync(0xffffffffu, t, 2));
            t *= sl2e;
            float mn = fmaxf(mx1, t);
            float alpha = exp2f(mx1 - mn);
            float ps = 0.f;
            #pragma unroll
            for (int nt = 0; nt < 8; nt++) {
                float p0 = exp2f(s[nt][2] * sl2e - mn);
                float p1 = exp2f(s[nt][3] * sl2e - mn);
                s[nt][2] = p0; s[nt][3] = p1; ps += p0 + p1;
            }
            ps += __shfl_xor_sync(0xffffffffu, ps, 1);
            ps += __shfl_xor_sync(0xffffffffu, ps, 2);
            l1 = l1 * alpha + ps; mx1 = mn;
            #pragma unroll
            for (int nt = 0; nt < 8; nt++) { o[nt][2] *= alpha; o[nt][3] *= alpha; }
        }

        // ---- O += P @ V : tf32, P relayout via shuffles (V pre-rounded) ----
        {
            const int src0 = 4 * r + (c >> 1);
            const int src1 = src0 + 2;
            const bool odd = (c & 1);
            #pragma unroll
            for (int kc = 0; kc < 8; kc++) {
                const int k8 = kc * 8;
                float t00 = __shfl_sync(0xffffffffu, s[kc][0], src0);
                float t01 = __shfl_sync(0xffffffffu, s[kc][1], src0);
                float t02 = __shfl_sync(0xffffffffu, s[kc][2], src0);
                float t03 = __shfl_sync(0xffffffffu, s[kc][3], src0);
                float t10 = __shfl_sync(0xffffffffu, s[kc][0], src1);
                float t11 = __shfl_sync(0xffffffffu, s[kc][1], src1);
                float t12 = __shfl_sync(0xffffffffu, s[kc][2], src1);
                float t13 = __shfl_sync(0xffffffffu, s[kc][3], src1);
                uint32_t a0 = tf32u(odd ? t01 : t00);
                uint32_t a1 = tf32u(odd ? t03 : t02);
                uint32_t a2 = tf32u(odd ? t11 : t10);
                uint32_t a3 = tf32u(odd ? t13 : t12);
                #pragma unroll
                for (int nt = 0; nt < 8; nt++) {
                    uint32_t b0 = __float_as_uint(Vs[(k8 + c) * VST + nt * 8 + r]);
                    uint32_t b1 = __float_as_uint(Vs[(k8 + c + 4) * VST + nt * 8 + r]);
                    mma_tf32(o[nt][0], o[nt][1], o[nt][2], o[nt][3], a0, a1, a2, a3, b0, b1);
                }
            }
        }
        __syncthreads();   // all warps done with stage[buf] before it is reloaded
    }

    // ---- epilogue ----
    const float inv0 = 1.f / l0;
    const float inv1 = 1.f / l1;
    const size_t row0 = (size_t)(b * SEQ + q0 + m0 + r) * DMODEL + h * HD;
    const size_t row1 = row0 + (size_t)8 * DMODEL;
    #pragma unroll
    for (int nt = 0; nt < 8; nt++) {
        const int col = nt * 8 + 2 * c;
        *(float2*)(out + row0 + col) = make_float2(o[nt][0] * inv0, o[nt][1] * inv0);
        *(float2*)(out + row1 + col) = make_float2(o[nt][2] * inv1, o[nt][3] * inv1);
    }
}

// ---------------------------------------------------------------------------
extern "C" void kernel_launch(void* const* d_in, const int* in_sizes, int n_in,
                              void* d_out, int out_size)
{
    const float* x     = (const float*)d_in[0];
    const float* w_qkv = (const float*)d_in[1];
    const float* w_out = (const float*)d_in[2];
    const float* b_out = (const float*)d_in[3];
    float* out = (float*)d_out;

    float *qkv, *att;
    uint32_t *kh, *kl;
    cudaGetSymbolAddress((void**)&qkv, g_qkv);
    cudaGetSymbolAddress((void**)&att, g_att);
    cudaGetSymbolAddress((void**)&kh, g_kh);
    cudaGetSymbolAddress((void**)&kl, g_kl);

    // 1) QKV projection (tf32 mma)
    {
        dim3 grid(QKV_N / BN, ROWS / BM);
        tf32_gemm_kernel<<<grid, 256>>>(x, w_qkv, nullptr, qkv, ROWS, QKV_N, DMODEL);
    }

    // 1.5) prep: split K to packed bf16 hi/lo; round V to tf32 in place
    {
        int nk = BATCH * NHEADS * SEQ * 32;
        prep_k_kernel<<<nk / 256, 256>>>(qkv, kh, kl);
        int nv = BATCH * NHEADS * SEQ * 16;
        round_v_kernel<<<nv / 256, 256>>>(qkv);
    }

    // 2) Flash attention v5 (pure-cp.async loader, double-buffered K/V)
    {
        cudaFuncSetAttribute(flash_tc_kernel,
                             cudaFuncAttributeMaxDynamicSharedMemorySize, FLASH_SMEM);
        dim3 grid(SEQ / FBM, BATCH * NHEADS);
        flash_tc_kernel<<<grid, 256, FLASH_SMEM>>>(qkv, kh, kl, att);
    }

    // 3) Output projection + bias
    {
        dim3 grid(DMODEL / BN, ROWS / BM);
        tf32_gemm_kernel<<<grid, 256>>>(att, w_out, b_out, out, ROWS, DMODEL, DMODEL);
    }
}